// round 2
// baseline (speedup 1.0000x reference)
#include <cuda_runtime.h>
#include <math.h>

#define B_     16
#define TMAX   4096
#define DMODEL 1024
#define H_     16
#define DH     64
#define NSPLIT 32
#define CHUNK  128   // TMAX / NSPLIT

// -------- scratch (device globals; no allocation allowed) --------
__device__ float2 g_tab[TMAX * 32];                 // cos/sin per (t, i)
__device__ float  g_qkvp[3 * B_ * H_ * 4 * DH];     // qkv partials over 4 e-chunks
__device__ float  g_pm[B_ * H_ * NSPLIT];           // split max
__device__ float  g_pl[B_ * H_ * NSPLIT];           // split sumexp
__device__ float  g_pacc[B_ * H_ * NSPLIT * DH];    // split weighted V accum
__device__ float  g_o[B_ * H_ * DH];                // attention output

// ================= RoPE table =================
// inv_freq computed in double then rounded to f32 (matches reference's fp32
// inv_freq to ~1 ulp); angle formed in f32 like the reference, then cos/sin
// evaluated accurately via fp64 range reduction (angles up to ~4095 rad).
__global__ void k_table() {
    int idx = blockIdx.x * blockDim.x + threadIdx.x;
    if (idx >= TMAX * 32) return;
    int t = idx >> 5, i = idx & 31;
    double invd = exp(-(double)i * (log(10000.0) / 32.0));
    float invf = (float)invd;
    float angf = (float)t * invf;          // f32 rounding, same as reference
    double ang = (double)angf;
    const double TWO_PI = 6.283185307179586476925286766559;
    double r = ang - TWO_PI * floor(ang / TWO_PI + 0.5);
    float rf = (float)r;
    float s, c;
    sincosf(rf, &s, &c);
    g_tab[idx] = make_float2(c, s);
}

// ================= QKV projection (partials over 4 e-chunks) =================
// grid (4 e-chunks, 16 heads, 3 tensors), 256 threads.
// Each weight element is read exactly once across the whole grid.
__global__ void k_proj(const float* __restrict__ x,
                       const float* __restrict__ Wq,
                       const float* __restrict__ Wk,
                       const float* __restrict__ Wv) {
    int ec = blockIdx.x;   // e-chunk (256 e's)
    int h  = blockIdx.y;
    int tz = blockIdx.z;   // 0=q 1=k 2=v
    const float* W = (tz == 0) ? Wq : (tz == 1) ? Wk : Wv;

    __shared__ float xs[256 * 16];         // [e_local][b]
    int tid = threadIdx.x;
    for (int idx = tid; idx < 256 * 16; idx += 256) {
        int el = idx >> 4, b = idx & 15;
        xs[el * 16 + b] = x[b * DMODEL + ec * 256 + el];
    }
    __syncthreads();

    int d = tid & 63, esub = tid >> 6;     // 4 sub-chunks of 64 e
    float acc[16];
#pragma unroll
    for (int b = 0; b < 16; ++b) acc[b] = 0.f;

    const float4* xs4 = (const float4*)xs;
    const float* Wbase = W + ((ec * 256) * H_ + h) * DH + d;
#pragma unroll 4
    for (int ee = 0; ee < 64; ++ee) {
        int el = esub * 64 + ee;
        float w = Wbase[el * (H_ * DH)];
        float4 xa = xs4[el * 4 + 0];
        float4 xb = xs4[el * 4 + 1];
        float4 xc = xs4[el * 4 + 2];
        float4 xd = xs4[el * 4 + 3];
        acc[0]  += xa.x * w;  acc[1]  += xa.y * w;  acc[2]  += xa.z * w;  acc[3]  += xa.w * w;
        acc[4]  += xb.x * w;  acc[5]  += xb.y * w;  acc[6]  += xb.z * w;  acc[7]  += xb.w * w;
        acc[8]  += xc.x * w;  acc[9]  += xc.y * w;  acc[10] += xc.z * w;  acc[11] += xc.w * w;
        acc[12] += xd.x * w;  acc[13] += xd.y * w;  acc[14] += xd.z * w;  acc[15] += xd.w * w;
    }

    __shared__ float sred[4][16 * 64];
#pragma unroll
    for (int b = 0; b < 16; ++b) sred[esub][b * 64 + d] = acc[b];
    __syncthreads();

    for (int idx = tid; idx < 1024; idx += 256) {
        int b = idx >> 6, dd = idx & 63;
        float v = sred[0][idx] + sred[1][idx] + sred[2][idx] + sred[3][idx];
        g_qkvp[(((tz * B_ + b) * H_ + h) * 4 + ec) * DH + dd] = v;
    }
}

// ================= Attention (split over T) =================
// grid (256 bh, 32 splits), 256 threads (8 warps). Warp handles timesteps
// t = t0 + w + 8*i. Lane l holds dims (l, l+32) -> RoPE pair is local.
__global__ void k_attn(const float* __restrict__ ck,
                       const float* __restrict__ cv,
                       const float* __restrict__ bq,
                       const float* __restrict__ bk,
                       const float* __restrict__ bv,
                       const int*   __restrict__ cip) {
    int bh = blockIdx.x;
    int b = bh >> 4, h = bh & 15;
    int ci = *cip;
    int Tlen = ci + 1;
    int t0 = blockIdx.y * CHUNK;
    int sidx = bh * NSPLIT + blockIdx.y;

    if (t0 >= Tlen) {
        if (threadIdx.x == 0) { g_pm[sidx] = -1e30f; g_pl[sidx] = 0.f; }
        if (threadIdx.x < DH) g_pacc[sidx * DH + threadIdx.x] = 0.f;
        return;
    }
    int t1 = min(t0 + CHUNK, Tlen);

    int w = threadIdx.x >> 5, l = threadIdx.x & 31;

    // q (sum 4 e-chunk partials + bias), then rope at position ci
    const float* qp = g_qkvp + (((0 * B_ + b) * H_ + h) * 4) * DH;
    float q1 = qp[l]      + qp[64 + l]  + qp[128 + l] + qp[192 + l] + bq[h * DH + l];
    float q2 = qp[32 + l] + qp[96 + l]  + qp[160 + l] + qp[224 + l] + bq[h * DH + 32 + l];
    float2 qcs = g_tab[ci * 32 + l];
    float qr1 = q1 * qcs.x - q2 * qcs.y;
    float qr2 = q1 * qcs.y + q2 * qcs.x;

    float m = -1e30f, lsum = 0.f, a1 = 0.f, a2 = 0.f;

    for (int t = t0 + w; t < t1; t += 8) {
        float k1, k2, v1, v2;
        if (t == ci) {
            const float* kp = g_qkvp + (((1 * B_ + b) * H_ + h) * 4) * DH;
            k1 = kp[l]      + kp[64 + l] + kp[128 + l] + kp[192 + l] + bk[h * DH + l];
            k2 = kp[32 + l] + kp[96 + l] + kp[160 + l] + kp[224 + l] + bk[h * DH + 32 + l];
            const float* vp = g_qkvp + (((2 * B_ + b) * H_ + h) * 4) * DH;
            v1 = vp[l]      + vp[64 + l] + vp[128 + l] + vp[192 + l] + bv[h * DH + l];
            v2 = vp[32 + l] + vp[96 + l] + vp[160 + l] + vp[224 + l] + bv[h * DH + 32 + l];
        } else {
            long off = (((long)b * TMAX + t) * H_ + h) * DH;
            k1 = ck[off + l];  k2 = ck[off + 32 + l];
            v1 = cv[off + l];  v2 = cv[off + 32 + l];
        }
        float2 cs = g_tab[t * 32 + l];
        float kr1 = k1 * cs.x - k2 * cs.y;
        float kr2 = k1 * cs.y + k2 * cs.x;
        float s = kr1 * qr1 + kr2 * qr2;
        s += __shfl_xor_sync(0xffffffffu, s, 16);
        s += __shfl_xor_sync(0xffffffffu, s, 8);
        s += __shfl_xor_sync(0xffffffffu, s, 4);
        s += __shfl_xor_sync(0xffffffffu, s, 2);
        s += __shfl_xor_sync(0xffffffffu, s, 1);
        s *= 0.125f;                         // 1/sqrt(64)

        float nm = fmaxf(m, s);
        float corr = __expf(m - nm);
        float p = __expf(s - nm);
        lsum = lsum * corr + p;
        a1 = a1 * corr + p * v1;
        a2 = a2 * corr + p * v2;
        m = nm;
    }

    __shared__ float sm[8], sl[8], sacc[8][DH];
    if (l == 0) { sm[w] = m; sl[w] = lsum; }
    sacc[w][l] = a1;
    sacc[w][32 + l] = a2;
    __syncthreads();

    if (threadIdx.x < DH) {
        int d = threadIdx.x;
        float M = sm[0];
#pragma unroll
        for (int i = 1; i < 8; ++i) M = fmaxf(M, sm[i]);
        float L = 0.f, A = 0.f;
#pragma unroll
        for (int i = 0; i < 8; ++i) {
            float e = __expf(sm[i] - M);
            L += sl[i] * e;
            A += sacc[i][d] * e;
        }
        g_pacc[sidx * DH + d] = A;
        if (d == 0) { g_pm[sidx] = M; g_pl[sidx] = L; }
    }
}

// ================= Split reduction =================
__global__ void k_red() {
    int bh = blockIdx.x;
    int d = threadIdx.x;
    float M = -1e30f;
#pragma unroll
    for (int s = 0; s < NSPLIT; ++s) M = fmaxf(M, g_pm[bh * NSPLIT + s]);
    float L = 0.f, A = 0.f;
#pragma unroll
    for (int s = 0; s < NSPLIT; ++s) {
        float e = __expf(g_pm[bh * NSPLIT + s] - M);
        L += g_pl[bh * NSPLIT + s] * e;
        A += g_pacc[(bh * NSPLIT + s) * DH + d] * e;
    }
    g_o[bh * DH + d] = A / L;
}

// ================= Output projection =================
// grid (4 e-chunks, 16 b), 256 threads
__global__ void k_out(const float* __restrict__ Wo,
                      const float* __restrict__ bo,
                      float* __restrict__ out) {
    int b = blockIdx.y;
    int e = blockIdx.x * 256 + threadIdx.x;
    __shared__ float os[1024];
    for (int i = threadIdx.x; i < 1024; i += 256) os[i] = g_o[b * 1024 + i];
    __syncthreads();
    float acc = bo[e];
#pragma unroll 8
    for (int hd = 0; hd < 1024; ++hd)
        acc += os[hd] * Wo[hd * 1024 + e];
    out[b * DMODEL + e] = acc;
}

extern "C" void kernel_launch(void* const* d_in, const int* in_sizes, int n_in,
                              void* d_out, int out_size) {
    const float* x   = (const float*)d_in[0];
    const float* cK  = (const float*)d_in[1];
    const float* cV  = (const float*)d_in[2];
    const float* Wq  = (const float*)d_in[3];
    const float* bq  = (const float*)d_in[4];
    const float* Wk  = (const float*)d_in[5];
    const float* bk  = (const float*)d_in[6];
    const float* Wv  = (const float*)d_in[7];
    const float* bv  = (const float*)d_in[8];
    const float* Wo  = (const float*)d_in[9];
    const float* bo  = (const float*)d_in[10];
    const int*   ci  = (const int*)d_in[11];
    float* out = (float*)d_out;

    k_table<<<(TMAX * 32) / 256, 256>>>();
    k_proj<<<dim3(4, H_, 3), 256>>>(x, Wq, Wk, Wv);
    k_attn<<<dim3(B_ * H_, NSPLIT), 256>>>(cK, cV, bq, bk, bv, ci);
    k_red<<<B_ * H_, DH>>>();
    k_out<<<dim3(4, B_), 256>>>(Wo, bo, out);
}

// round 3
// speedup vs baseline: 1.1708x; 1.1708x over previous
#include <cuda_runtime.h>
#include <math.h>

#define B_     16
#define TMAX   4096
#define DMODEL 1024
#define H_     16
#define DH     64
#define NSPLIT 32
#define CHUNK  128   // TMAX / NSPLIT, 8 warps * 16 t

// -------- scratch (device globals; no allocation allowed) --------
__device__ float2 g_tab[TMAX * 32];                 // cos/sin per (t, i)
__device__ float  g_qkvp[3 * B_ * H_ * 4 * DH];     // qkv partials over 4 e-chunks
__device__ float  g_pm[B_ * H_ * NSPLIT];           // split max
__device__ float  g_pl[B_ * H_ * NSPLIT];           // split sumexp
__device__ float  g_pacc[B_ * H_ * NSPLIT * DH];    // split weighted V accum
__device__ float  g_o[B_ * H_ * DH];                // attention output
__device__ float  g_outp[4 * B_ * DMODEL];          // out-proj split-k partials

// ================= RoPE table =================
// Same math as the passing R1 kernel (fp64 inv_freq -> f32, f32 angle, fp64
// range reduction), but the expensive fp64 exp/log runs once per block for the
// 32 distinct inv_freq values instead of once per thread.
__global__ void k_table() {
    __shared__ float sinv[32];
    int tid = threadIdx.x;
    if (tid < 32) {
        double invd = exp(-(double)tid * (log(10000.0) / 32.0));
        sinv[tid] = (float)invd;
    }
    __syncthreads();
    int idx = blockIdx.x * 256 + tid;     // grid 512 -> 131072 entries
    int t = idx >> 5, i = idx & 31;
    float angf = (float)t * sinv[i];       // f32 rounding, same as reference
    double ang = (double)angf;
    const double TWO_PI = 6.283185307179586476925286766559;
    double r = ang - TWO_PI * floor(ang / TWO_PI + 0.5);
    float s, c;
    sincosf((float)r, &s, &c);
    g_tab[idx] = make_float2(c, s);
}

// ================= QKV projection (partials over 4 e-chunks) =================
__global__ void k_proj(const float* __restrict__ x,
                       const float* __restrict__ Wq,
                       const float* __restrict__ Wk,
                       const float* __restrict__ Wv) {
    int ec = blockIdx.x;   // e-chunk (256 e's)
    int h  = blockIdx.y;
    int tz = blockIdx.z;   // 0=q 1=k 2=v
    const float* W = (tz == 0) ? Wq : (tz == 1) ? Wk : Wv;

    __shared__ float xs[256 * 16];         // [e_local][b]
    int tid = threadIdx.x;
    for (int idx = tid; idx < 256 * 16; idx += 256) {
        int el = idx >> 4, b = idx & 15;
        xs[el * 16 + b] = x[b * DMODEL + ec * 256 + el];
    }
    __syncthreads();

    int d = tid & 63, esub = tid >> 6;     // 4 sub-chunks of 64 e
    float acc[16];
#pragma unroll
    for (int b = 0; b < 16; ++b) acc[b] = 0.f;

    const float4* xs4 = (const float4*)xs;
    const float* Wbase = W + ((ec * 256) * H_ + h) * DH + d;
#pragma unroll 4
    for (int ee = 0; ee < 64; ++ee) {
        int el = esub * 64 + ee;
        float w = Wbase[el * (H_ * DH)];
        float4 xa = xs4[el * 4 + 0];
        float4 xb = xs4[el * 4 + 1];
        float4 xc = xs4[el * 4 + 2];
        float4 xd = xs4[el * 4 + 3];
        acc[0]  += xa.x * w;  acc[1]  += xa.y * w;  acc[2]  += xa.z * w;  acc[3]  += xa.w * w;
        acc[4]  += xb.x * w;  acc[5]  += xb.y * w;  acc[6]  += xb.z * w;  acc[7]  += xb.w * w;
        acc[8]  += xc.x * w;  acc[9]  += xc.y * w;  acc[10] += xc.z * w;  acc[11] += xc.w * w;
        acc[12] += xd.x * w;  acc[13] += xd.y * w;  acc[14] += xd.z * w;  acc[15] += xd.w * w;
    }

    __shared__ float sred[4][16 * 64];
#pragma unroll
    for (int b = 0; b < 16; ++b) sred[esub][b * 64 + d] = acc[b];
    __syncthreads();

    for (int idx = tid; idx < 1024; idx += 256) {
        int b = idx >> 6, dd = idx & 63;
        float v = sred[0][idx] + sred[1][idx] + sred[2][idx] + sred[3][idx];
        g_qkvp[(((tz * B_ + b) * H_ + h) * 4 + ec) * DH + dd] = v;
    }
}

// ================= Attention (split over T, deferred softmax) =================
// grid (256 bh, 32 splits), 256 threads (8 warps). Warp w owns the 16
// contiguous timesteps [t0 + 16w, t0 + 16w + 16). Pass 1 computes all 16
// scores (independent butterflies -> full ILP/MLP); softmax is done offline
// per warp; pass 2 streams V with known weights. No loop-carried chains.
__global__ void k_attn(const float* __restrict__ ck,
                       const float* __restrict__ cv,
                       const float* __restrict__ bq,
                       const float* __restrict__ bk,
                       const float* __restrict__ bv,
                       const int*   __restrict__ cip) {
    int bh = blockIdx.x;
    int b = bh >> 4, h = bh & 15;
    int ci = *cip;
    int Tlen = ci + 1;
    int t0 = blockIdx.y * CHUNK;
    int sidx = bh * NSPLIT + blockIdx.y;

    if (t0 >= Tlen) {
        if (threadIdx.x == 0) { g_pm[sidx] = -1e30f; g_pl[sidx] = 0.f; }
        if (threadIdx.x < DH) g_pacc[sidx * DH + threadIdx.x] = 0.f;
        return;
    }
    int t1 = min(t0 + CHUNK, Tlen);

    int w = threadIdx.x >> 5, l = threadIdx.x & 31;

    // q (sum 4 e-chunk partials + bias), rope at position ci
    const float* qp = g_qkvp + (((0 * B_ + b) * H_ + h) * 4) * DH;
    float q1 = qp[l]      + qp[64 + l]  + qp[128 + l] + qp[192 + l] + bq[h * DH + l];
    float q2 = qp[32 + l] + qp[96 + l]  + qp[160 + l] + qp[224 + l] + bq[h * DH + 32 + l];
    float2 qcs = g_tab[ci * 32 + l];
    float qr1 = q1 * qcs.x - q2 * qcs.y;
    float qr2 = q1 * qcs.y + q2 * qcs.x;

    // freshly computed k/v at slot ci (hoisted out of the loops; selects inside)
    const float* kp = g_qkvp + (((1 * B_ + b) * H_ + h) * 4) * DH;
    float kci1 = kp[l]      + kp[64 + l] + kp[128 + l] + kp[192 + l] + bk[h * DH + l];
    float kci2 = kp[32 + l] + kp[96 + l] + kp[160 + l] + kp[224 + l] + bk[h * DH + 32 + l];
    const float* vp = g_qkvp + (((2 * B_ + b) * H_ + h) * 4) * DH;
    float vci1 = vp[l]      + vp[64 + l] + vp[128 + l] + vp[192 + l] + bv[h * DH + l];
    float vci2 = vp[32 + l] + vp[96 + l] + vp[160 + l] + vp[224 + l] + bv[h * DH + 32 + l];

    int tw = t0 + w * 16;
    const float* kbase = ck + ((long)b * TMAX + tw) * (H_ * DH) + h * DH + l;
    const float* vbase = cv + ((long)b * TMAX + tw) * (H_ * DH) + h * DH + l;

    // ---- pass 1: scores ----
    float s[16];
#pragma unroll
    for (int i = 0; i < 16; ++i) {
        int t = tw + i;
        float k1 = kbase[i * (H_ * DH)];
        float k2 = kbase[i * (H_ * DH) + 32];
        if (t == ci) { k1 = kci1; k2 = kci2; }
        float2 cs = g_tab[t * 32 + l];
        float kr1 = k1 * cs.x - k2 * cs.y;
        float kr2 = k1 * cs.y + k2 * cs.x;
        float d = kr1 * qr1 + kr2 * qr2;
        d += __shfl_xor_sync(0xffffffffu, d, 16);
        d += __shfl_xor_sync(0xffffffffu, d, 8);
        d += __shfl_xor_sync(0xffffffffu, d, 4);
        d += __shfl_xor_sync(0xffffffffu, d, 2);
        d += __shfl_xor_sync(0xffffffffu, d, 1);
        s[i] = (t < t1) ? d * 0.125f : -1e30f;
    }

    // ---- offline softmax (per warp) ----
    float m = s[0];
#pragma unroll
    for (int i = 1; i < 16; ++i) m = fmaxf(m, s[i]);
    float lsum = 0.f;
#pragma unroll
    for (int i = 0; i < 16; ++i) {
        float p = (s[i] > -5e29f) ? __expf(s[i] - m) : 0.f;
        s[i] = p;
        lsum += p;
    }

    // ---- pass 2: weighted V ----
    float a1 = 0.f, a2 = 0.f;
#pragma unroll
    for (int i = 0; i < 16; ++i) {
        int t = tw + i;
        float v1 = vbase[i * (H_ * DH)];
        float v2 = vbase[i * (H_ * DH) + 32];
        if (t == ci) { v1 = vci1; v2 = vci2; }
        a1 += s[i] * v1;
        a2 += s[i] * v2;
    }

    // ---- block combine over 8 warps ----
    __shared__ float sm[8], sl[8], sacc[8][DH];
    if (l == 0) { sm[w] = m; sl[w] = lsum; }
    sacc[w][l] = a1;
    sacc[w][32 + l] = a2;
    __syncthreads();

    if (threadIdx.x < DH) {
        int d = threadIdx.x;
        float M = sm[0];
#pragma unroll
        for (int i = 1; i < 8; ++i) M = fmaxf(M, sm[i]);
        float L = 0.f, A = 0.f;
#pragma unroll
        for (int i = 0; i < 8; ++i) {
            float e = __expf(sm[i] - M);
            L += sl[i] * e;
            A += sacc[i][d] * e;
        }
        g_pacc[sidx * DH + d] = A;
        if (d == 0) { g_pm[sidx] = M; g_pl[sidx] = L; }
    }
}

// ================= Split reduction =================
// grid 256 (bh), 256 threads: 4 split-groups of 8, unrolled -> MLP 8.
__global__ void k_red() {
    int bh = blockIdx.x;
    int d = threadIdx.x & 63, sg = threadIdx.x >> 6;
    float M = -1e30f;
#pragma unroll
    for (int s = 0; s < NSPLIT; ++s) M = fmaxf(M, g_pm[bh * NSPLIT + s]);
    float L = 0.f, A = 0.f;
#pragma unroll
    for (int j = 0; j < 8; ++j) {
        int s = sg * 8 + j;
        float e = __expf(g_pm[bh * NSPLIT + s] - M);
        L += g_pl[bh * NSPLIT + s] * e;
        A += g_pacc[(bh * NSPLIT + s) * DH + d] * e;
    }
    __shared__ float sA[4][DH];
    __shared__ float sL[4];
    sA[sg][d] = A;
    if (d == 0) sL[sg] = L;
    __syncthreads();
    if (threadIdx.x < DH) {
        int dd = threadIdx.x;
        float Lt = sL[0] + sL[1] + sL[2] + sL[3];
        float At = sA[0][dd] + sA[1][dd] + sA[2][dd] + sA[3][dd];
        g_o[bh * DH + dd] = At / Lt;
    }
}

// ================= Output projection (split-K) =================
// k_out1: grid (4 e-chunks, 16 b, 4 hd-chunks), 256 threads.
__global__ void k_out1(const float* __restrict__ Wo) {
    int ec = blockIdx.x, b = blockIdx.y, kc = blockIdx.z;
    int tid = threadIdx.x;
    __shared__ float os[256];
    os[tid] = g_o[b * 1024 + kc * 256 + tid];
    __syncthreads();
    int e = ec * 256 + tid;
    const float* Wp = Wo + (kc * 256) * 1024 + e;
    float acc = 0.f;
#pragma unroll 16
    for (int hd = 0; hd < 256; ++hd)
        acc += os[hd] * Wp[hd * 1024];
    g_outp[(kc * 16 + b) * 1024 + e] = acc;
}

// k_out2: sum 4 partials + bias. grid 64, 256 threads.
__global__ void k_out2(const float* __restrict__ bo, float* __restrict__ out) {
    int idx = blockIdx.x * 256 + threadIdx.x;   // b*1024 + e
    float v = bo[idx & 1023];
#pragma unroll
    for (int kc = 0; kc < 4; ++kc) v += g_outp[kc * (B_ * 1024) + idx];
    out[idx] = v;
}

extern "C" void kernel_launch(void* const* d_in, const int* in_sizes, int n_in,
                              void* d_out, int out_size) {
    const float* x   = (const float*)d_in[0];
    const float* cK  = (const float*)d_in[1];
    const float* cV  = (const float*)d_in[2];
    const float* Wq  = (const float*)d_in[3];
    const float* bq  = (const float*)d_in[4];
    const float* Wk  = (const float*)d_in[5];
    const float* bk  = (const float*)d_in[6];
    const float* Wv  = (const float*)d_in[7];
    const float* bv  = (const float*)d_in[8];
    const float* Wo  = (const float*)d_in[9];
    const float* bo  = (const float*)d_in[10];
    const int*   ci  = (const int*)d_in[11];
    float* out = (float*)d_out;

    k_table<<<(TMAX * 32) / 256, 256>>>();
    k_proj<<<dim3(4, H_, 3), 256>>>(x, Wq, Wk, Wv);
    k_attn<<<dim3(B_ * H_, NSPLIT), 256>>>(cK, cV, bq, bk, bv, ci);
    k_red<<<B_ * H_, 256>>>();
    k_out1<<<dim3(4, B_, 4), 256>>>(Wo);
    k_out2<<<B_ * 1024 / 256, 256>>>(bo, out);
}

// round 6
// speedup vs baseline: 1.5478x; 1.3219x over previous
#include <cuda_runtime.h>
#include <math.h>

#define B_     16
#define TMAX   4096
#define DMODEL 1024
#define H_     16
#define DH     64
#define NSPLIT 64
#define CHUNK  64    // TMAX / NSPLIT; 8 warps * 8 t

// -------- scratch (device globals; no allocation allowed) --------
__device__ float4 g_tab4[TMAX * 16];                // (c0,s0,c1,s1) per (t, j)
__device__ float  g_qkvp[3 * B_ * H_ * 4 * DH];     // qkv partials over 4 e-chunks
__device__ float  g_pm[B_ * H_ * NSPLIT];           // split max
__device__ float  g_pl[B_ * H_ * NSPLIT];           // split sumexp
__device__ float  g_pacc[B_ * H_ * NSPLIT * DH];    // split weighted V accum
__device__ float  g_o[B_ * H_ * DH];                // attention output
__device__ float  g_outp[4 * B_ * DMODEL];          // out-proj split-k partials

// ================= RoPE table =================
// fp64 inv_freq -> f32 (matches reference to ~1 ulp); f32 angle like the
// reference; accurate fp64 range reduction via multiply (no fp64 divide).
__global__ void k_table() {
    __shared__ float sinv[32];
    int tid = threadIdx.x;
    if (tid < 32) {
        double invd = exp(-(double)tid * (log(10000.0) / 32.0));
        sinv[tid] = (float)invd;
    }
    __syncthreads();
    int idx = blockIdx.x * 256 + tid;     // grid 512 -> 131072 entries
    int t = idx >> 5, i = idx & 31;
    float angf = (float)t * sinv[i];       // f32 rounding, same as reference
    double ang = (double)angf;
    const double TWO_PI     = 6.283185307179586476925286766559;
    const double INV_TWO_PI = 0.15915494309189533576888376337251;
    double r = ang - TWO_PI * floor(ang * INV_TWO_PI + 0.5);
    float s, c;
    sincosf((float)r, &s, &c);
    // float4 (t, j) = {c_2j, s_2j, c_2j+1, s_2j+1}  ==  float2 (t, i) = (c_i, s_i)
    ((float2*)g_tab4)[idx] = make_float2(c, s);
}

__global__ void k_dummy() {}   // pads launch order so k_attn is profiled launch

// ================= QKV projection (partials over 4 e-chunks) =================
__global__ void k_proj(const float* __restrict__ x,
                       const float* __restrict__ Wq,
                       const float* __restrict__ Wk,
                       const float* __restrict__ Wv) {
    int ec = blockIdx.x;   // e-chunk (256 e's)
    int h  = blockIdx.y;
    int tz = blockIdx.z;   // 0=q 1=k 2=v
    const float* W = (tz == 0) ? Wq : (tz == 1) ? Wk : Wv;

    __shared__ float xs[256 * 16];         // [e_local][b]
    int tid = threadIdx.x;
    for (int idx = tid; idx < 256 * 16; idx += 256) {
        int el = idx >> 4, b = idx & 15;
        xs[el * 16 + b] = x[b * DMODEL + ec * 256 + el];
    }
    __syncthreads();

    int d = tid & 63, esub = tid >> 6;     // 4 sub-chunks of 64 e
    float acc[16];
#pragma unroll
    for (int b = 0; b < 16; ++b) acc[b] = 0.f;

    const float4* xs4 = (const float4*)xs;
    const float* Wbase = W + ((ec * 256) * H_ + h) * DH + d;
#pragma unroll 4
    for (int ee = 0; ee < 64; ++ee) {
        int el = esub * 64 + ee;
        float w = Wbase[el * (H_ * DH)];
        float4 xa = xs4[el * 4 + 0];
        float4 xb = xs4[el * 4 + 1];
        float4 xc = xs4[el * 4 + 2];
        float4 xd = xs4[el * 4 + 3];
        acc[0]  += xa.x * w;  acc[1]  += xa.y * w;  acc[2]  += xa.z * w;  acc[3]  += xa.w * w;
        acc[4]  += xb.x * w;  acc[5]  += xb.y * w;  acc[6]  += xb.z * w;  acc[7]  += xb.w * w;
        acc[8]  += xc.x * w;  acc[9]  += xc.y * w;  acc[10] += xc.z * w;  acc[11] += xc.w * w;
        acc[12] += xd.x * w;  acc[13] += xd.y * w;  acc[14] += xd.z * w;  acc[15] += xd.w * w;
    }

    __shared__ float sred[4][16 * 64];
#pragma unroll
    for (int b = 0; b < 16; ++b) sred[esub][b * 64 + d] = acc[b];
    __syncthreads();

    for (int idx = tid; idx < 1024; idx += 256) {
        int b = idx >> 6, dd = idx & 63;
        float v = sred[0][idx] + sred[1][idx] + sred[2][idx] + sred[3][idx];
        g_qkvp[(((tz * B_ + b) * H_ + h) * 4 + ec) * DH + dd] = v;
    }
}

// ================= Attention (split over T, folded-RoPE scoring) =================
// score(t) = sum_d k[d] * (c_{f(d)}(t) * A_d + s_{f(d)}(t) * B_d)
// with A_d = qrot[d], B_d = (d<32 ? qrot[d+32] : -qrot[d-32]).
// Lane l owns contiguous dims (2l, 2l+1) -> K/V are float2 loads, table float4.
// grid (256 bh, 64 splits), 256 threads (8 warps), 8 timesteps per warp.
__global__ void __launch_bounds__(256, 3)
k_attn(const float* __restrict__ ck,
       const float* __restrict__ cv,
       const float* __restrict__ bq,
       const float* __restrict__ bk,
       const float* __restrict__ bv,
       const int*   __restrict__ cip) {
    int bh = blockIdx.x;
    int b = bh >> 4, h = bh & 15;
    int ci = *cip;
    int Tlen = ci + 1;
    int t0 = blockIdx.y * CHUNK;
    int sidx = bh * NSPLIT + blockIdx.y;
    int tid = threadIdx.x;

    if (t0 >= Tlen) {
        if (tid == 0) { g_pm[sidx] = -1e30f; g_pl[sidx] = 0.f; }
        if (tid < DH) g_pacc[sidx * DH + tid] = 0.f;
        return;
    }
    int t1 = min(t0 + CHUNK, Tlen);

    int w = tid >> 5, l = tid & 31;

    // ---- setup (warp 0): rotated q, fresh k/v at slot ci -> smem ----
    __shared__ float sqr[64], skci[64], svci[64];
    if (tid < 32) {
        const float* qp = g_qkvp + (((0 * B_ + b) * H_ + h) * 4) * DH;
        float q1 = qp[tid]      + qp[64 + tid]  + qp[128 + tid] + qp[192 + tid] + bq[h * DH + tid];
        float q2 = qp[32 + tid] + qp[96 + tid]  + qp[160 + tid] + qp[224 + tid] + bq[h * DH + 32 + tid];
        float2 qcs = ((const float2*)g_tab4)[ci * 32 + tid];
        sqr[tid]      = q1 * qcs.x - q2 * qcs.y;
        sqr[tid + 32] = q1 * qcs.y + q2 * qcs.x;
        const float* kp = g_qkvp + (((1 * B_ + b) * H_ + h) * 4) * DH;
        skci[tid]      = kp[tid]      + kp[64 + tid] + kp[128 + tid] + kp[192 + tid] + bk[h * DH + tid];
        skci[tid + 32] = kp[32 + tid] + kp[96 + tid] + kp[160 + tid] + kp[224 + tid] + bk[h * DH + 32 + tid];
        const float* vp = g_qkvp + (((2 * B_ + b) * H_ + h) * 4) * DH;
        svci[tid]      = vp[tid]      + vp[64 + tid] + vp[128 + tid] + vp[192 + tid] + bv[h * DH + tid];
        svci[tid + 32] = vp[32 + tid] + vp[96 + tid] + vp[160 + tid] + vp[224 + tid] + bv[h * DH + 32 + tid];
    }
    __syncthreads();

    int d0 = 2 * l;                      // this lane's dims: d0, d0+1
    float A0 = sqr[d0], A1 = sqr[d0 + 1];
    float B0 = (l < 16) ? sqr[d0 + 32] : -sqr[d0 - 32];
    float B1 = (l < 16) ? sqr[d0 + 33] : -sqr[d0 - 31];
    float2 kci = make_float2(skci[d0], skci[d0 + 1]);
    float2 vci = make_float2(svci[d0], svci[d0 + 1]);

    int tw = t0 + w * 8;
    const float* kbase = ck + ((long)b * TMAX + tw) * (H_ * DH) + h * DH + d0;
    const float* vbase = cv + ((long)b * TMAX + tw) * (H_ * DH) + h * DH + d0;
    int j = l & 15;                      // table float4 index within row

    // ---- pass 1: 8 independent scores ----
    float s[8];
#pragma unroll
    for (int i = 0; i < 8; ++i) {
        int t = tw + i;
        float2 kv = *(const float2*)(kbase + i * (H_ * DH));
        if (t == ci) kv = kci;
        float4 cs = g_tab4[t * 16 + j];
        float dd = kv.x * (cs.x * A0 + cs.y * B0) + kv.y * (cs.z * A1 + cs.w * B1);
        dd += __shfl_xor_sync(0xffffffffu, dd, 16);
        dd += __shfl_xor_sync(0xffffffffu, dd, 8);
        dd += __shfl_xor_sync(0xffffffffu, dd, 4);
        dd += __shfl_xor_sync(0xffffffffu, dd, 2);
        dd += __shfl_xor_sync(0xffffffffu, dd, 1);
        s[i] = (t < t1) ? dd * 0.125f : -1e30f;
    }

    // ---- offline softmax (per warp) ----
    float m = s[0];
#pragma unroll
    for (int i = 1; i < 8; ++i) m = fmaxf(m, s[i]);
    float lsum = 0.f;
#pragma unroll
    for (int i = 0; i < 8; ++i) {
        float p = (s[i] > -5e29f) ? __expf(s[i] - m) : 0.f;
        s[i] = p;
        lsum += p;
    }

    // ---- pass 2: weighted V ----
    float2 a = make_float2(0.f, 0.f);
#pragma unroll
    for (int i = 0; i < 8; ++i) {
        int t = tw + i;
        float2 vv = *(const float2*)(vbase + i * (H_ * DH));
        if (t == ci) vv = vci;
        a.x += s[i] * vv.x;
        a.y += s[i] * vv.y;
    }

    // ---- block combine over 8 warps ----
    __shared__ float sm[8], sl[8], sacc[8][DH];
    if (l == 0) { sm[w] = m; sl[w] = lsum; }
    sacc[w][d0]     = a.x;
    sacc[w][d0 + 1] = a.y;
    __syncthreads();

    if (tid < DH) {
        int d = tid;
        float M = sm[0];
#pragma unroll
        for (int i = 1; i < 8; ++i) M = fmaxf(M, sm[i]);
        float L = 0.f, A = 0.f;
#pragma unroll
        for (int i = 0; i < 8; ++i) {
            float e = __expf(sm[i] - M);
            L += sl[i] * e;
            A += sacc[i][d] * e;
        }
        g_pacc[sidx * DH + d] = A;
        if (d == 0) { g_pm[sidx] = M; g_pl[sidx] = L; }
    }
}

// ================= Split reduction =================
// grid 256 (bh), 256 threads: 4 split-groups of 16, unrolled -> MLP 16.
__global__ void k_red() {
    int bh = blockIdx.x;
    int d = threadIdx.x & 63, sg = threadIdx.x >> 6;
    float M = -1e30f;
#pragma unroll
    for (int s = 0; s < NSPLIT; ++s) M = fmaxf(M, g_pm[bh * NSPLIT + s]);
    float L = 0.f, A = 0.f;
#pragma unroll
    for (int jj = 0; jj < NSPLIT / 4; ++jj) {
        int s = sg * (NSPLIT / 4) + jj;
        float e = __expf(g_pm[bh * NSPLIT + s] - M);
        L += g_pl[bh * NSPLIT + s] * e;
        A += g_pacc[(bh * NSPLIT + s) * DH + d] * e;
    }
    __shared__ float sA[4][DH];
    __shared__ float sL[4];
    sA[sg][d] = A;
    if (d == 0) sL[sg] = L;
    __syncthreads();
    if (threadIdx.x < DH) {
        int dd = threadIdx.x;
        float Lt = sL[0] + sL[1] + sL[2] + sL[3];
        float At = sA[0][dd] + sA[1][dd] + sA[2][dd] + sA[3][dd];
        g_o[bh * DH + dd] = At / Lt;
    }
}

// ================= Output projection (split-K) =================
__global__ void k_out1(const float* __restrict__ Wo) {
    int ec = blockIdx.x, b = blockIdx.y, kc = blockIdx.z;
    int tid = threadIdx.x;
    __shared__ float os[256];
    os[tid] = g_o[b * 1024 + kc * 256 + tid];
    __syncthreads();
    int e = ec * 256 + tid;
    const float* Wp = Wo + (kc * 256) * 1024 + e;
    float acc = 0.f;
#pragma unroll 16
    for (int hd = 0; hd < 256; ++hd)
        acc += os[hd] * Wp[hd * 1024];
    g_outp[(kc * 16 + b) * 1024 + e] = acc;
}

__global__ void k_out2(const float* __restrict__ bo, float* __restrict__ out) {
    int idx = blockIdx.x * 256 + threadIdx.x;   // b*1024 + e
    float v = bo[idx & 1023];
#pragma unroll
    for (int kc = 0; kc < 4; ++kc) v += g_outp[kc * (B_ * 1024) + idx];
    out[idx] = v;
}

extern "C" void kernel_launch(void* const* d_in, const int* in_sizes, int n_in,
                              void* d_out, int out_size) {
    const float* x   = (const float*)d_in[0];
    const float* cK  = (const float*)d_in[1];
    const float* cV  = (const float*)d_in[2];
    const float* Wq  = (const float*)d_in[3];
    const float* bq  = (const float*)d_in[4];
    const float* Wk  = (const float*)d_in[5];
    const float* bk  = (const float*)d_in[6];
    const float* Wv  = (const float*)d_in[7];
    const float* bv  = (const float*)d_in[8];
    const float* Wo  = (const float*)d_in[9];
    const float* bo  = (const float*)d_in[10];
    const int*   ci  = (const int*)d_in[11];
    float* out = (float*)d_out;

    k_table<<<(TMAX * 32) / 256, 256>>>();
    k_proj<<<dim3(4, H_, 3), 256>>>(x, Wq, Wk, Wv);
    k_dummy<<<1, 32>>>();   // pad: puts k_attn at the profiled launch index
    k_attn<<<dim3(B_ * H_, NSPLIT), 256>>>(cK, cV, bq, bk, bv, ci);
    k_red<<<B_ * H_, 256>>>();
    k_out1<<<dim3(4, B_, 4), 256>>>(Wo);
    k_out2<<<B_ * 1024 / 256, 256>>>(bo, out);
}

// round 7
// speedup vs baseline: 1.8512x; 1.1960x over previous
#include <cuda_runtime.h>
#include <math.h>

#define B_     16
#define TMAX   4096
#define DMODEL 1024
#define H_     16
#define DH     64
#define NSPLIT 64
#define CHUNK  64    // TMAX / NSPLIT; 8 warps * 8 t

// -------- scratch (device globals; no allocation allowed) --------
__device__ float4 g_tab4[TMAX * 16];                // (c0,s0,c1,s1) per (t, j)
__device__ float  g_qkvp[3 * B_ * H_ * 4 * DH];     // qkv partials over 4 e-chunks
__device__ float  g_pm[B_ * H_ * NSPLIT];           // split max
__device__ float  g_pl[B_ * H_ * NSPLIT];           // split sumexp
__device__ float  g_pacc[B_ * H_ * NSPLIT * DH];    // split weighted V accum
__device__ float  g_outp[4 * B_ * DMODEL];          // out-proj split-k partials

// ================= Stage 1: RoPE table + QKV projection (fused grid) =================
// blocks [0,512): cos/sin table.  blocks [512,704): qkv projection.
__global__ void k_stage1(const float* __restrict__ x,
                         const float* __restrict__ Wq,
                         const float* __restrict__ Wk,
                         const float* __restrict__ Wv) {
    int tid = threadIdx.x;

    if (blockIdx.x < 512) {
        // ---- RoPE table: fp64 inv_freq -> f32, f32 angle (matches reference),
        //      fp64 multiply-based range reduction, f32 sincos ----
        __shared__ float sinv[32];
        if (tid < 32) {
            double invd = exp(-(double)tid * (log(10000.0) / 32.0));
            sinv[tid] = (float)invd;
        }
        __syncthreads();
        int idx = blockIdx.x * 256 + tid;     // 131072 entries
        int t = idx >> 5, i = idx & 31;
        float angf = (float)t * sinv[i];
        double ang = (double)angf;
        const double TWO_PI     = 6.283185307179586476925286766559;
        const double INV_TWO_PI = 0.15915494309189533576888376337251;
        double r = ang - TWO_PI * floor(ang * INV_TWO_PI + 0.5);
        float s, c;
        sincosf((float)r, &s, &c);
        ((float2*)g_tab4)[idx] = make_float2(c, s);
        return;
    }

    // ---- QKV projection (partials over 4 e-chunks) ----
    int bidx = blockIdx.x - 512;           // 0..191
    int ec = bidx & 3, h = (bidx >> 2) & 15, tz = bidx >> 6;   // tz: 0=q 1=k 2=v
    const float* W = (tz == 0) ? Wq : (tz == 1) ? Wk : Wv;

    __shared__ float xs[256 * 16];         // [e_local][b]
    for (int idx = tid; idx < 256 * 16; idx += 256) {
        int el = idx >> 4, b = idx & 15;
        xs[el * 16 + b] = x[b * DMODEL + ec * 256 + el];
    }
    __syncthreads();

    int d = tid & 63, esub = tid >> 6;     // 4 sub-chunks of 64 e
    float acc[16];
#pragma unroll
    for (int b = 0; b < 16; ++b) acc[b] = 0.f;

    const float4* xs4 = (const float4*)xs;
    const float* Wbase = W + ((ec * 256) * H_ + h) * DH + d;
#pragma unroll 4
    for (int ee = 0; ee < 64; ++ee) {
        int el = esub * 64 + ee;
        float w = Wbase[el * (H_ * DH)];
        float4 xa = xs4[el * 4 + 0];
        float4 xb = xs4[el * 4 + 1];
        float4 xc = xs4[el * 4 + 2];
        float4 xd = xs4[el * 4 + 3];
        acc[0]  += xa.x * w;  acc[1]  += xa.y * w;  acc[2]  += xa.z * w;  acc[3]  += xa.w * w;
        acc[4]  += xb.x * w;  acc[5]  += xb.y * w;  acc[6]  += xb.z * w;  acc[7]  += xb.w * w;
        acc[8]  += xc.x * w;  acc[9]  += xc.y * w;  acc[10] += xc.z * w;  acc[11] += xc.w * w;
        acc[12] += xd.x * w;  acc[13] += xd.y * w;  acc[14] += xd.z * w;  acc[15] += xd.w * w;
    }

    __shared__ float sred[4][16 * 64];
#pragma unroll
    for (int b = 0; b < 16; ++b) sred[esub][b * 64 + d] = acc[b];
    __syncthreads();

    for (int idx = tid; idx < 1024; idx += 256) {
        int b = idx >> 6, dd = idx & 63;
        float v = sred[0][idx] + sred[1][idx] + sred[2][idx] + sred[3][idx];
        g_qkvp[(((tz * B_ + b) * H_ + h) * 4 + ec) * DH + dd] = v;
    }
}

// ================= Attention (split over T, folded-RoPE scoring) =================
// score(t) = sum_d k[d] * (c_{f(d)}(t) * A_d + s_{f(d)}(t) * B_d)
// grid (256 bh, 64 splits), 256 threads (8 warps), 8 timesteps per warp.
__global__ void __launch_bounds__(256, 4)
k_attn(const float* __restrict__ ck,
       const float* __restrict__ cv,
       const float* __restrict__ bq,
       const float* __restrict__ bk,
       const float* __restrict__ bv,
       const int*   __restrict__ cip) {
    int bh = blockIdx.x;
    int b = bh >> 4, h = bh & 15;
    int ci = *cip;
    int Tlen = ci + 1;
    int t0 = blockIdx.y * CHUNK;
    int sidx = bh * NSPLIT + blockIdx.y;
    int tid = threadIdx.x;

    if (t0 >= Tlen) {
        if (tid == 0) { g_pm[sidx] = -1e30f; g_pl[sidx] = 0.f; }
        if (tid < DH) g_pacc[sidx * DH + tid] = 0.f;
        return;
    }
    int t1 = min(t0 + CHUNK, Tlen);

    int w = tid >> 5, l = tid & 31;

    // ---- setup (warp 0): rotated q, fresh k/v at slot ci -> smem ----
    __shared__ float sqr[64], skci[64], svci[64];
    if (tid < 32) {
        const float* qp = g_qkvp + (((0 * B_ + b) * H_ + h) * 4) * DH;
        float q1 = qp[tid]      + qp[64 + tid]  + qp[128 + tid] + qp[192 + tid] + bq[h * DH + tid];
        float q2 = qp[32 + tid] + qp[96 + tid]  + qp[160 + tid] + qp[224 + tid] + bq[h * DH + 32 + tid];
        float2 qcs = ((const float2*)g_tab4)[ci * 32 + tid];
        sqr[tid]      = q1 * qcs.x - q2 * qcs.y;
        sqr[tid + 32] = q1 * qcs.y + q2 * qcs.x;
        const float* kp = g_qkvp + (((1 * B_ + b) * H_ + h) * 4) * DH;
        skci[tid]      = kp[tid]      + kp[64 + tid] + kp[128 + tid] + kp[192 + tid] + bk[h * DH + tid];
        skci[tid + 32] = kp[32 + tid] + kp[96 + tid] + kp[160 + tid] + kp[224 + tid] + bk[h * DH + 32 + tid];
        const float* vp = g_qkvp + (((2 * B_ + b) * H_ + h) * 4) * DH;
        svci[tid]      = vp[tid]      + vp[64 + tid] + vp[128 + tid] + vp[192 + tid] + bv[h * DH + tid];
        svci[tid + 32] = vp[32 + tid] + vp[96 + tid] + vp[160 + tid] + vp[224 + tid] + bv[h * DH + 32 + tid];
    }
    __syncthreads();

    int d0 = 2 * l;                      // this lane's dims: d0, d0+1
    float A0 = sqr[d0], A1 = sqr[d0 + 1];
    float B0 = (l < 16) ? sqr[d0 + 32] : -sqr[d0 - 32];
    float B1 = (l < 16) ? sqr[d0 + 33] : -sqr[d0 - 31];
    float2 kci = make_float2(skci[d0], skci[d0 + 1]);
    float2 vci = make_float2(svci[d0], svci[d0 + 1]);

    int tw = t0 + w * 8;
    const float* kbase = ck + ((long)b * TMAX + tw) * (H_ * DH) + h * DH + d0;
    const float* vbase = cv + ((long)b * TMAX + tw) * (H_ * DH) + h * DH + d0;
    int j = l & 15;                      // table float4 index within row

    // ---- pass 1: 8 independent scores ----
    float s[8];
#pragma unroll
    for (int i = 0; i < 8; ++i) {
        int t = tw + i;
        float2 kv = *(const float2*)(kbase + i * (H_ * DH));
        if (t == ci) kv = kci;
        float4 cs = g_tab4[t * 16 + j];
        float dd = kv.x * (cs.x * A0 + cs.y * B0) + kv.y * (cs.z * A1 + cs.w * B1);
        dd += __shfl_xor_sync(0xffffffffu, dd, 16);
        dd += __shfl_xor_sync(0xffffffffu, dd, 8);
        dd += __shfl_xor_sync(0xffffffffu, dd, 4);
        dd += __shfl_xor_sync(0xffffffffu, dd, 2);
        dd += __shfl_xor_sync(0xffffffffu, dd, 1);
        s[i] = (t < t1) ? dd * 0.125f : -1e30f;
    }

    // ---- offline softmax (per warp) ----
    float m = s[0];
#pragma unroll
    for (int i = 1; i < 8; ++i) m = fmaxf(m, s[i]);
    float lsum = 0.f;
#pragma unroll
    for (int i = 0; i < 8; ++i) {
        float p = (s[i] > -5e29f) ? __expf(s[i] - m) : 0.f;
        s[i] = p;
        lsum += p;
    }

    // ---- pass 2: weighted V ----
    float2 a = make_float2(0.f, 0.f);
#pragma unroll
    for (int i = 0; i < 8; ++i) {
        int t = tw + i;
        float2 vv = *(const float2*)(vbase + i * (H_ * DH));
        if (t == ci) vv = vci;
        a.x += s[i] * vv.x;
        a.y += s[i] * vv.y;
    }

    // ---- block combine over 8 warps ----
    __shared__ float sm[8], sl[8], sacc[8][DH];
    if (l == 0) { sm[w] = m; sl[w] = lsum; }
    sacc[w][d0]     = a.x;
    sacc[w][d0 + 1] = a.y;
    __syncthreads();

    if (tid < DH) {
        int d = tid;
        float M = sm[0];
#pragma unroll
        for (int i = 1; i < 8; ++i) M = fmaxf(M, sm[i]);
        float L = 0.f, A = 0.f;
#pragma unroll
        for (int i = 0; i < 8; ++i) {
            float e = __expf(sm[i] - M);
            L += sl[i] * e;
            A += sacc[i][d] * e;
        }
        g_pacc[sidx * DH + d] = A;
        if (d == 0) { g_pm[sidx] = M; g_pl[sidx] = L; }
    }
}

// ================= Fused split-reduction + out-proj pass 1 =================
// grid (4 ec, 16 b, 4 kc), 256 threads. Each block reduces the 4 heads of its
// kc chunk (exp computed once per (bh,split), shared via smem), builds the
// 256 o-values in smem, then computes out partials for its 256-e chunk.
__global__ void k_redout(const float* __restrict__ Wo) {
    int ec = blockIdx.x, b = blockIdx.y, kc = blockIdx.z;
    int tid = threadIdx.x;
    int hl = tid >> 6;          // head-local 0..3
    int s  = tid & 63;          // split id (phase A) / dim d (phase B)
    int bh = b * H_ + kc * 4 + hl;

    __shared__ float sPm[4][NSPLIT], sE[4][NSPLIT], sLE[4][NSPLIT];
    sPm[hl][s] = g_pm[bh * NSPLIT + s];
    __syncthreads();
    float M = -1e30f;
#pragma unroll 8
    for (int k = 0; k < NSPLIT; ++k) M = fmaxf(M, sPm[hl][k]);
    float e = __expf(sPm[hl][s] - M);
    sE[hl][s]  = e;
    sLE[hl][s] = g_pl[bh * NSPLIT + s] * e;
    __syncthreads();

    int d = s;
    float L = 0.f, A = 0.f;
#pragma unroll 8
    for (int k = 0; k < NSPLIT; ++k) {
        A += g_pacc[(bh * NSPLIT + k) * DH + d] * sE[hl][k];
        L += sLE[hl][k];
    }
    __shared__ float os[256];
    os[tid] = A / L;
    __syncthreads();

    int e2 = ec * 256 + tid;
    const float* Wp = Wo + (kc * 256) * DMODEL + e2;
    float acc = 0.f;
#pragma unroll 16
    for (int hd = 0; hd < 256; ++hd)
        acc += os[hd] * Wp[hd * DMODEL];
    g_outp[(kc * B_ + b) * DMODEL + e2] = acc;
}

// ================= Out-proj pass 2: sum 4 partials + bias =================
__global__ void k_out2(const float* __restrict__ bo, float* __restrict__ out) {
    int idx = blockIdx.x * 256 + threadIdx.x;   // b*1024 + e
    float v = bo[idx & (DMODEL - 1)];
#pragma unroll
    for (int kc = 0; kc < 4; ++kc) v += g_outp[kc * (B_ * DMODEL) + idx];
    out[idx] = v;
}

extern "C" void kernel_launch(void* const* d_in, const int* in_sizes, int n_in,
                              void* d_out, int out_size) {
    const float* x   = (const float*)d_in[0];
    const float* cK  = (const float*)d_in[1];
    const float* cV  = (const float*)d_in[2];
    const float* Wq  = (const float*)d_in[3];
    const float* bq  = (const float*)d_in[4];
    const float* Wk  = (const float*)d_in[5];
    const float* bk  = (const float*)d_in[6];
    const float* Wv  = (const float*)d_in[7];
    const float* bv  = (const float*)d_in[8];
    const float* Wo  = (const float*)d_in[9];
    const float* bo  = (const float*)d_in[10];
    const int*   ci  = (const int*)d_in[11];
    float* out = (float*)d_out;

    k_stage1<<<704, 256>>>(x, Wq, Wk, Wv);
    k_attn<<<dim3(B_ * H_, NSPLIT), 256>>>(cK, cV, bq, bk, bv, ci);
    k_redout<<<dim3(4, B_, 4), 256>>>(Wo);
    k_out2<<<B_ * DMODEL / 256, 256>>>(bo, out);
}